// round 5
// baseline (speedup 1.0000x reference)
#include <cuda_runtime.h>
#include <cuda_bf16.h>
#include <cstdint>
#include <cstddef>

#define D_IN  12544
#define D_HID 1024
#define MAXN  16000

// ---------------- device scratch (allocation-free rule) ----------------
__device__ __align__(1024) __nv_bfloat16 g_Xhi[(size_t)MAXN * D_IN];
__device__ __align__(1024) __nv_bfloat16 g_Xlo[(size_t)MAXN * D_IN];
__device__ __align__(1024) __nv_bfloat16 g_W1hi[(size_t)D_HID * D_IN];  // [N][K]
__device__ __align__(1024) __nv_bfloat16 g_W1lo[(size_t)D_HID * D_IN];
__device__ __align__(1024) __nv_bfloat16 g_W2hi[(size_t)D_HID * D_HID];
__device__ __align__(1024) __nv_bfloat16 g_W2lo[(size_t)D_HID * D_HID];
__device__ __align__(1024) __nv_bfloat16 g_h1hi[(size_t)MAXN * D_HID];
__device__ __align__(1024) __nv_bfloat16 g_h1lo[(size_t)MAXN * D_HID];
__device__ float g_h2[(size_t)MAXN * D_HID];

// ---------------- asm helpers ----------------
__device__ __forceinline__ uint32_t smem_u32(const void* p) {
    uint32_t a;
    asm("{ .reg .u64 t; cvta.to.shared.u64 t, %1; cvt.u32.u64 %0, t; }" : "=r"(a) : "l"(p));
    return a;
}
__device__ __forceinline__ void cp16(uint32_t dst, const void* src) {
    asm volatile("cp.async.cg.shared.global [%0], [%1], 16;" :: "r"(dst), "l"(src));
}
__device__ __forceinline__ void cp_commit() {
    asm volatile("cp.async.commit_group;" ::: "memory");
}
template <int N>
__device__ __forceinline__ void cp_wait() {
    asm volatile("cp.async.wait_group %0;" :: "n"(N) : "memory");
}
__device__ __forceinline__ void ldm_x4(uint32_t& r0, uint32_t& r1, uint32_t& r2, uint32_t& r3, uint32_t addr) {
    asm volatile("ldmatrix.sync.aligned.m8n8.x4.shared.b16 {%0,%1,%2,%3}, [%4];"
                 : "=r"(r0), "=r"(r1), "=r"(r2), "=r"(r3) : "r"(addr));
}
__device__ __forceinline__ void mma16816(float* c, const uint32_t* a, uint32_t b0, uint32_t b1) {
    asm volatile(
        "mma.sync.aligned.m16n8k16.row.col.f32.bf16.bf16.f32 "
        "{%0,%1,%2,%3}, {%4,%5,%6,%7}, {%8,%9}, {%0,%1,%2,%3};"
        : "+f"(c[0]), "+f"(c[1]), "+f"(c[2]), "+f"(c[3])
        : "r"(a[0]), "r"(a[1]), "r"(a[2]), "r"(a[3]), "r"(b0), "r"(b1));
}

// ---------------- GEMM: C[M,N] = act(A[M,K] @ B[N,K]^T + bias), bf16 hi/lo x3 ----------------
// CTA tile BM=128, BN=256, BK=32. 3-stage cp.async pipeline.
// 16 warps (4 M x 4 N), warp tile 32x64 -> MMA:LDSM ratio 4.
#define LDS       40                    // smem stride in halves (80B) - conflict free
#define TILE_A_B  (128 * LDS * 2)       // 10240 B per [128][32] bf16 tile
#define TILE_B_B  (256 * LDS * 2)       // 20480 B per [256][32] bf16 tile
#define OFF_AHI   0
#define OFF_ALO   (TILE_A_B)
#define OFF_BHI   (2 * TILE_A_B)
#define OFF_BLO   (2 * TILE_A_B + TILE_B_B)
#define STAGE_B   (2 * TILE_A_B + 2 * TILE_B_B)   // 61440
#define NSTAGE    3
#define SM_TOTAL  (NSTAGE * STAGE_B)               // 184320

template <int NROWS>
__device__ __forceinline__ void load_tile(uint32_t sdst, const __nv_bfloat16* __restrict__ g,
                                          int row0, int K, int k0, int tid)
{
    const char* gb = (const char*)(g + (size_t)row0 * K + k0);
#pragma unroll
    for (int p = 0; p < NROWS / 128; p++) {
        const int r = (tid >> 2) + p * 128;
        const int c = tid & 3;
        cp16(sdst + r * (LDS * 2) + c * 16, gb + (size_t)r * K * 2 + c * 16);
    }
}

template <int WRITE_HILO>
__global__ __launch_bounds__(512, 1)
void gemm_mma_x3(const __nv_bfloat16* __restrict__ Ahi, const __nv_bfloat16* __restrict__ Alo,
                 const __nv_bfloat16* __restrict__ Bhi, const __nv_bfloat16* __restrict__ Blo,
                 const float* __restrict__ bias,
                 __nv_bfloat16* __restrict__ Chi, __nv_bfloat16* __restrict__ Clo,
                 float* __restrict__ Cf,
                 int K, int N)
{
    extern __shared__ char smem[];
    const uint32_t sb = smem_u32(smem);
    const int tid  = threadIdx.x;
    const int wid  = tid >> 5;
    const int lane = tid & 31;
    const int wm   = wid & 3;        // 0..3 (M)
    const int wn   = wid >> 2;       // 0..3 (N)

    const int bm = blockIdx.y * 128;
    const int bn = blockIdx.x * 256;
    const int NK = K / 32;

    float acc[2][8][4];
#pragma unroll
    for (int mt = 0; mt < 2; mt++)
#pragma unroll
        for (int nb = 0; nb < 8; nb++)
#pragma unroll
            for (int q = 0; q < 4; q++) acc[mt][nb][q] = 0.0f;

    // prologue: prefetch stages 0, 1
#pragma unroll
    for (int s = 0; s < NSTAGE - 1; s++) {
        const uint32_t st = sb + s * STAGE_B;
        load_tile<128>(st + OFF_AHI, Ahi, bm, K, s * 32, tid);
        load_tile<128>(st + OFF_ALO, Alo, bm, K, s * 32, tid);
        load_tile<256>(st + OFF_BHI, Bhi, bn, K, s * 32, tid);
        load_tile<256>(st + OFF_BLO, Blo, bn, K, s * 32, tid);
        cp_commit();
    }

    // ldmatrix lane addressing (within-tile offsets, in bytes)
    const uint32_t a_lane_off = ((lane & 15) * LDS + (lane >> 4) * 8) * 2;
    const uint32_t b_lane_off = ((((lane >> 4) * 8) + (lane & 7)) * LDS + (((lane >> 3) & 1) * 8)) * 2;
    const uint32_t a_base_off = (wm * 32) * (LDS * 2);
    const uint32_t b_base_off = (wn * 64) * (LDS * 2);

    for (int c = 0; c < NK; c++) {
        cp_wait<NSTAGE - 2>();
        __syncthreads();

        // prefetch stage c + NSTAGE-1 into the slot just freed
        const int pf = c + NSTAGE - 1;
        if (pf < NK) {
            const uint32_t st = sb + (pf % NSTAGE) * STAGE_B;
            load_tile<128>(st + OFF_AHI, Ahi, bm, K, pf * 32, tid);
            load_tile<128>(st + OFF_ALO, Alo, bm, K, pf * 32, tid);
            load_tile<256>(st + OFF_BHI, Bhi, bn, K, pf * 32, tid);
            load_tile<256>(st + OFF_BLO, Blo, bn, K, pf * 32, tid);
        }
        cp_commit();

        const uint32_t st = sb + (c % NSTAGE) * STAGE_B;
        const uint32_t sAh = st + OFF_AHI + a_base_off + a_lane_off;
        const uint32_t sAl = st + OFF_ALO + a_base_off + a_lane_off;
        const uint32_t sBh = st + OFF_BHI + b_base_off + b_lane_off;
        const uint32_t sBl = st + OFF_BLO + b_base_off + b_lane_off;

#pragma unroll
        for (int kk = 0; kk < 2; kk++) {
            const uint32_t ko = kk * 16 * 2;
            uint32_t ah[2][4], al[2][4];
#pragma unroll
            for (int mt = 0; mt < 2; mt++) {
                ldm_x4(ah[mt][0], ah[mt][1], ah[mt][2], ah[mt][3], sAh + mt * 16 * (LDS * 2) + ko);
                ldm_x4(al[mt][0], al[mt][1], al[mt][2], al[mt][3], sAl + mt * 16 * (LDS * 2) + ko);
            }
            // process B in 16-column pairs to bound register pressure
#pragma unroll
            for (int p = 0; p < 4; p++) {
                uint32_t bh[4], bl[4];
                ldm_x4(bh[0], bh[1], bh[2], bh[3], sBh + p * 16 * (LDS * 2) + ko);
                ldm_x4(bl[0], bl[1], bl[2], bl[3], sBl + p * 16 * (LDS * 2) + ko);
#pragma unroll
                for (int mt = 0; mt < 2; mt++) {
#pragma unroll
                    for (int half = 0; half < 2; half++) {
                        float* a0 = acc[mt][2 * p + half];
                        const int o = half * 2;
                        mma16816(a0, ah[mt], bh[o], bh[o + 1]);   // hi*hi
                        mma16816(a0, ah[mt], bl[o], bl[o + 1]);   // hi*lo
                        mma16816(a0, al[mt], bh[o], bh[o + 1]);   // lo*hi
                    }
                }
            }
        }
        __syncthreads();
    }

    // ---------------- epilogue: bias + ReLU ----------------
#pragma unroll
    for (int mt = 0; mt < 2; mt++) {
        const int row0 = bm + wm * 32 + mt * 16 + (lane >> 2);
#pragma unroll
        for (int nb = 0; nb < 8; nb++) {
            const int col = bn + wn * 64 + nb * 8 + (lane & 3) * 2;
            const float bx = bias[col];
            const float by = bias[col + 1];
            float y0 = fmaxf(acc[mt][nb][0] + bx, 0.0f);
            float y1 = fmaxf(acc[mt][nb][1] + by, 0.0f);
            float y2 = fmaxf(acc[mt][nb][2] + bx, 0.0f);
            float y3 = fmaxf(acc[mt][nb][3] + by, 0.0f);
            if (WRITE_HILO) {
                __nv_bfloat16 h0 = __float2bfloat16(y0), h1 = __float2bfloat16(y1);
                __nv_bfloat16 h2 = __float2bfloat16(y2), h3 = __float2bfloat16(y3);
                __nv_bfloat16 l0 = __float2bfloat16(y0 - __bfloat162float(h0));
                __nv_bfloat16 l1 = __float2bfloat16(y1 - __bfloat162float(h1));
                __nv_bfloat16 l2 = __float2bfloat16(y2 - __bfloat162float(h2));
                __nv_bfloat16 l3 = __float2bfloat16(y3 - __bfloat162float(h3));
                *(__nv_bfloat162*)(Chi + (size_t)row0 * N + col)       = __nv_bfloat162(h0, h1);
                *(__nv_bfloat162*)(Chi + (size_t)(row0 + 8) * N + col) = __nv_bfloat162(h2, h3);
                *(__nv_bfloat162*)(Clo + (size_t)row0 * N + col)       = __nv_bfloat162(l0, l1);
                *(__nv_bfloat162*)(Clo + (size_t)(row0 + 8) * N + col) = __nv_bfloat162(l2, l3);
            } else {
                *(float2*)(Cf + (size_t)row0 * N + col)       = make_float2(y0, y1);
                *(float2*)(Cf + (size_t)(row0 + 8) * N + col) = make_float2(y2, y3);
            }
        }
    }
}

// ---------------- conversion kernels ----------------
__global__ __launch_bounds__(256)
void split_f32(const float* __restrict__ in, __nv_bfloat16* __restrict__ hi,
               __nv_bfloat16* __restrict__ lo, size_t n4)
{
    size_t i = (size_t)blockIdx.x * blockDim.x + threadIdx.x;
    if (i >= n4) return;
    float4 v = ((const float4*)in)[i];
    __nv_bfloat16 h0 = __float2bfloat16(v.x), h1 = __float2bfloat16(v.y);
    __nv_bfloat16 h2 = __float2bfloat16(v.z), h3 = __float2bfloat16(v.w);
    __nv_bfloat16 l0 = __float2bfloat16(v.x - __bfloat162float(h0));
    __nv_bfloat16 l1 = __float2bfloat16(v.y - __bfloat162float(h1));
    __nv_bfloat16 l2 = __float2bfloat16(v.z - __bfloat162float(h2));
    __nv_bfloat16 l3 = __float2bfloat16(v.w - __bfloat162float(h3));
    ((__nv_bfloat162*)hi)[i * 2 + 0] = __nv_bfloat162(h0, h1);
    ((__nv_bfloat162*)hi)[i * 2 + 1] = __nv_bfloat162(h2, h3);
    ((__nv_bfloat162*)lo)[i * 2 + 0] = __nv_bfloat162(l0, l1);
    ((__nv_bfloat162*)lo)[i * 2 + 1] = __nv_bfloat162(l2, l3);
}

// in: [K][N] fp32 row-major -> out hi/lo: [N][K] bf16 row-major
__global__ __launch_bounds__(256)
void transpose_split(const float* __restrict__ in, __nv_bfloat16* __restrict__ hi,
                     __nv_bfloat16* __restrict__ lo, int K, int N)
{
    __shared__ float t[32][33];
    const int k0 = blockIdx.y * 32;
    const int n0 = blockIdx.x * 32;
    const int tx = threadIdx.x;
    const int ty = threadIdx.y;
#pragma unroll
    for (int r = 0; r < 4; r++) {
        const int k = k0 + ty * 4 + r;
        t[ty * 4 + r][tx] = in[(size_t)k * N + n0 + tx];
    }
    __syncthreads();
#pragma unroll
    for (int r = 0; r < 4; r++) {
        const int n = n0 + ty * 4 + r;
        const float v = t[tx][ty * 4 + r];
        const __nv_bfloat16 h = __float2bfloat16(v);
        const __nv_bfloat16 l = __float2bfloat16(v - __bfloat162float(h));
        hi[(size_t)n * K + k0 + tx] = h;
        lo[(size_t)n * K + k0 + tx] = l;
    }
}

// ---------------- heads ----------------
__global__ __launch_bounds__(256)
void heads_kernel(const float* __restrict__ H,
                  const float* __restrict__ Wc, const float* __restrict__ bc,
                  const float* __restrict__ Wr, const float* __restrict__ br,
                  float* __restrict__ out, int M)
{
    const int warp = (blockIdx.x * blockDim.x + threadIdx.x) >> 5;
    const int lane = threadIdx.x & 31;
    if (warp >= M) return;

    const float* __restrict__ h = H + (size_t)warp * D_HID;
    float acc[16];
#pragma unroll
    for (int c = 0; c < 16; c++) acc[c] = 0.0f;

    for (int k = lane; k < D_HID; k += 32) {
        const float x = h[k];
        const float* wc = Wc + (size_t)k * 4;
#pragma unroll
        for (int c = 0; c < 4; c++) acc[c] = fmaf(x, wc[c], acc[c]);
        const float* wr = Wr + (size_t)k * 12;
#pragma unroll
        for (int c = 0; c < 12; c++) acc[4 + c] = fmaf(x, wr[c], acc[4 + c]);
    }
#pragma unroll
    for (int c = 0; c < 16; c++)
#pragma unroll
        for (int off = 16; off > 0; off >>= 1)
            acc[c] += __shfl_xor_sync(0xffffffffu, acc[c], off);

    if (lane < 4) {
        out[(size_t)warp * 4 + lane] = acc[lane] + bc[lane];
    } else if (lane < 16) {
        out[(size_t)M * 4 + (size_t)warp * 12 + (lane - 4)] = acc[lane] + br[lane - 4];
    }
}

// ---------------- host ----------------
extern "C" void kernel_launch(void* const* d_in, const int* in_sizes, int n_in,
                              void* d_out, int out_size)
{
    const float* X  = (const float*)d_in[0];
    const float* W1 = (const float*)d_in[1];
    const float* b1 = (const float*)d_in[2];
    const float* W2 = (const float*)d_in[3];
    const float* b2 = (const float*)d_in[4];
    const float* Wc = (const float*)d_in[5];
    const float* bc = (const float*)d_in[6];
    const float* Wr = (const float*)d_in[7];
    const float* br = (const float*)d_in[8];
    float* out = (float*)d_out;

    const int M = in_sizes[0] / D_IN;   // 16000

    __nv_bfloat16 *Xhi, *Xlo, *W1hi, *W1lo, *W2hi, *W2lo, *h1hi, *h1lo;
    float* h2;
    cudaGetSymbolAddress((void**)&Xhi, g_Xhi);
    cudaGetSymbolAddress((void**)&Xlo, g_Xlo);
    cudaGetSymbolAddress((void**)&W1hi, g_W1hi);
    cudaGetSymbolAddress((void**)&W1lo, g_W1lo);
    cudaGetSymbolAddress((void**)&W2hi, g_W2hi);
    cudaGetSymbolAddress((void**)&W2lo, g_W2lo);
    cudaGetSymbolAddress((void**)&h1hi, g_h1hi);
    cudaGetSymbolAddress((void**)&h1lo, g_h1lo);
    cudaGetSymbolAddress((void**)&h2, g_h2);

    // conversions
    {
        const size_t n4 = (size_t)M * D_IN / 4;
        split_f32<<<(unsigned)((n4 + 255) / 256), 256>>>(X, Xhi, Xlo, n4);
        dim3 tb(32, 8);
        transpose_split<<<dim3(D_HID / 32, D_IN / 32), tb>>>(W1, W1hi, W1lo, D_IN, D_HID);
        transpose_split<<<dim3(D_HID / 32, D_HID / 32), tb>>>(W2, W2hi, W2lo, D_HID, D_HID);
    }

    cudaFuncSetAttribute(gemm_mma_x3<1>, cudaFuncAttributeMaxDynamicSharedMemorySize, SM_TOTAL);
    cudaFuncSetAttribute(gemm_mma_x3<0>, cudaFuncAttributeMaxDynamicSharedMemorySize, SM_TOTAL);

    dim3 grid(D_HID / 256, M / 128);   // (4, 125) = 500 CTAs
    gemm_mma_x3<1><<<grid, 512, SM_TOTAL>>>(Xhi, Xlo, W1hi, W1lo, b1, h1hi, h1lo, nullptr, D_IN, D_HID);
    gemm_mma_x3<0><<<grid, 512, SM_TOTAL>>>(h1hi, h1lo, W2hi, W2lo, b2, nullptr, nullptr, h2, D_HID, D_HID);

    const int threads = 256;
    const int blocks = (M * 32 + threads - 1) / threads;
    heads_kernel<<<blocks, threads>>>(h2, Wc, bc, Wr, br, out, M);
}

// round 6
// speedup vs baseline: 1.1008x; 1.1008x over previous
#include <cuda_runtime.h>
#include <cuda_bf16.h>
#include <cstdint>
#include <cstddef>

#define D_IN  12544
#define D_HID 1024
#define MAXN  16000

// ---------------- device scratch (allocation-free rule) ----------------
__device__ __align__(1024) __nv_bfloat16 g_Xhi[(size_t)MAXN * D_IN];
__device__ __align__(1024) __nv_bfloat16 g_Xlo[(size_t)MAXN * D_IN];
__device__ __align__(1024) __nv_bfloat16 g_W1hi[(size_t)D_HID * D_IN];  // [N][K]
__device__ __align__(1024) __nv_bfloat16 g_W1lo[(size_t)D_HID * D_IN];
__device__ __align__(1024) __nv_bfloat16 g_W2hi[(size_t)D_HID * D_HID];
__device__ __align__(1024) __nv_bfloat16 g_W2lo[(size_t)D_HID * D_HID];
__device__ __align__(1024) __nv_bfloat16 g_h1hi[(size_t)MAXN * D_HID];
__device__ __align__(1024) __nv_bfloat16 g_h1lo[(size_t)MAXN * D_HID];
__device__ float g_h2[(size_t)MAXN * D_HID];

// ---------------- asm helpers ----------------
__device__ __forceinline__ uint32_t smem_u32(const void* p) {
    uint32_t a;
    asm("{ .reg .u64 t; cvta.to.shared.u64 t, %1; cvt.u32.u64 %0, t; }" : "=r"(a) : "l"(p));
    return a;
}
__device__ __forceinline__ void cp16(uint32_t dst, const void* src) {
    asm volatile("cp.async.cg.shared.global [%0], [%1], 16;" :: "r"(dst), "l"(src));
}
__device__ __forceinline__ void cp_commit() {
    asm volatile("cp.async.commit_group;" ::: "memory");
}
template <int N>
__device__ __forceinline__ void cp_wait() {
    asm volatile("cp.async.wait_group %0;" :: "n"(N) : "memory");
}
__device__ __forceinline__ void ldm_x4(uint32_t& r0, uint32_t& r1, uint32_t& r2, uint32_t& r3, uint32_t addr) {
    asm volatile("ldmatrix.sync.aligned.m8n8.x4.shared.b16 {%0,%1,%2,%3}, [%4];"
                 : "=r"(r0), "=r"(r1), "=r"(r2), "=r"(r3) : "r"(addr));
}
__device__ __forceinline__ void mma16816(float* c, const uint32_t* a, uint32_t b0, uint32_t b1) {
    asm volatile(
        "mma.sync.aligned.m16n8k16.row.col.f32.bf16.bf16.f32 "
        "{%0,%1,%2,%3}, {%4,%5,%6,%7}, {%8,%9}, {%0,%1,%2,%3};"
        : "+f"(c[0]), "+f"(c[1]), "+f"(c[2]), "+f"(c[3])
        : "r"(a[0]), "r"(a[1]), "r"(a[2]), "r"(a[3]), "r"(b0), "r"(b1));
}

// ---------------- GEMM: C[M,N] = act(A[M,K] @ B[N,K]^T + bias), bf16 hi/lo x3 ----------------
// CTA tile BM=128, BN=128, BK=32. 2-stage cp.async pipeline, 2 CTAs/SM.
// 8 warps (4 M x 2 N), warp tile 32x64 -> MMA:LDSM ratio 4.
#define LDS       40                    // smem stride in halves (80B) - conflict free
#define TILE_B    (128 * LDS * 2)       // 10240 B per [128][32] bf16 tile
#define OFF_AHI   0
#define OFF_ALO   (TILE_B)
#define OFF_BHI   (2 * TILE_B)
#define OFF_BLO   (3 * TILE_B)
#define STAGE_B   (4 * TILE_B)          // 40960
#define NSTAGE    2
#define SM_TOTAL  (NSTAGE * STAGE_B)    // 81920 -> 2 CTAs/SM

__device__ __forceinline__ void load_tile(uint32_t sdst, const __nv_bfloat16* __restrict__ g,
                                          int row0, int K, int k0, int tid)
{
    // 256 threads, 512 x 16B chunks: two chunks per thread
    const char* gb = (const char*)(g + (size_t)row0 * K + k0);
#pragma unroll
    for (int p = 0; p < 2; p++) {
        const int r = (tid >> 2) + p * 64;
        const int c = tid & 3;
        cp16(sdst + r * (LDS * 2) + c * 16, gb + (size_t)r * K * 2 + c * 16);
    }
}

template <int WRITE_HILO>
__global__ __launch_bounds__(256, 2)
void gemm_mma_x3(const __nv_bfloat16* __restrict__ Ahi, const __nv_bfloat16* __restrict__ Alo,
                 const __nv_bfloat16* __restrict__ Bhi, const __nv_bfloat16* __restrict__ Blo,
                 const float* __restrict__ bias,
                 __nv_bfloat16* __restrict__ Chi, __nv_bfloat16* __restrict__ Clo,
                 float* __restrict__ Cf,
                 int K, int N)
{
    extern __shared__ char smem[];
    const uint32_t sb = smem_u32(smem);
    const int tid  = threadIdx.x;
    const int wid  = tid >> 5;
    const int lane = tid & 31;
    const int wm   = wid & 3;        // 0..3 (M)
    const int wn   = wid >> 2;       // 0..1 (N)

    const int bm = blockIdx.y * 128;
    const int bn = blockIdx.x * 128;
    const int NK = K / 32;

    float acc[2][8][4];
#pragma unroll
    for (int mt = 0; mt < 2; mt++)
#pragma unroll
        for (int nb = 0; nb < 8; nb++)
#pragma unroll
            for (int q = 0; q < 4; q++) acc[mt][nb][q] = 0.0f;

    // prologue: prefetch stage 0
    {
        const uint32_t st = sb;
        load_tile(st + OFF_AHI, Ahi, bm, K, 0, tid);
        load_tile(st + OFF_ALO, Alo, bm, K, 0, tid);
        load_tile(st + OFF_BHI, Bhi, bn, K, 0, tid);
        load_tile(st + OFF_BLO, Blo, bn, K, 0, tid);
        cp_commit();
    }

    // ldmatrix lane addressing (within-tile offsets, in bytes)
    const uint32_t a_lane_off = ((lane & 15) * LDS + (lane >> 4) * 8) * 2;
    const uint32_t b_lane_off = ((((lane >> 4) * 8) + (lane & 7)) * LDS + (((lane >> 3) & 1) * 8)) * 2;
    const uint32_t a_base_off = (wm * 32) * (LDS * 2);
    const uint32_t b_base_off = (wn * 64) * (LDS * 2);

    for (int c = 0; c < NK; c++) {
        cp_wait<0>();
        __syncthreads();

        // prefetch next stage into the buffer freed one iteration ago
        const int pf = c + 1;
        if (pf < NK) {
            const uint32_t st = sb + (pf & 1) * STAGE_B;
            load_tile(st + OFF_AHI, Ahi, bm, K, pf * 32, tid);
            load_tile(st + OFF_ALO, Alo, bm, K, pf * 32, tid);
            load_tile(st + OFF_BHI, Bhi, bn, K, pf * 32, tid);
            load_tile(st + OFF_BLO, Blo, bn, K, pf * 32, tid);
        }
        cp_commit();

        const uint32_t st = sb + (c & 1) * STAGE_B;
        const uint32_t sAh = st + OFF_AHI + a_base_off + a_lane_off;
        const uint32_t sAl = st + OFF_ALO + a_base_off + a_lane_off;
        const uint32_t sBh = st + OFF_BHI + b_base_off + b_lane_off;
        const uint32_t sBl = st + OFF_BLO + b_base_off + b_lane_off;

#pragma unroll
        for (int kk = 0; kk < 2; kk++) {
            const uint32_t ko = kk * 16 * 2;
            uint32_t ah[2][4], al[2][4];
#pragma unroll
            for (int mt = 0; mt < 2; mt++) {
                ldm_x4(ah[mt][0], ah[mt][1], ah[mt][2], ah[mt][3], sAh + mt * 16 * (LDS * 2) + ko);
                ldm_x4(al[mt][0], al[mt][1], al[mt][2], al[mt][3], sAl + mt * 16 * (LDS * 2) + ko);
            }
            // process B in 16-column pairs to bound register pressure
#pragma unroll
            for (int p = 0; p < 4; p++) {
                uint32_t bh[4], bl[4];
                ldm_x4(bh[0], bh[1], bh[2], bh[3], sBh + p * 16 * (LDS * 2) + ko);
                ldm_x4(bl[0], bl[1], bl[2], bl[3], sBl + p * 16 * (LDS * 2) + ko);
#pragma unroll
                for (int mt = 0; mt < 2; mt++) {
#pragma unroll
                    for (int half = 0; half < 2; half++) {
                        float* a0 = acc[mt][2 * p + half];
                        const int o = half * 2;
                        mma16816(a0, ah[mt], bh[o], bh[o + 1]);   // hi*hi
                        mma16816(a0, ah[mt], bl[o], bl[o + 1]);   // hi*lo
                        mma16816(a0, al[mt], bh[o], bh[o + 1]);   // lo*hi
                    }
                }
            }
        }
        __syncthreads();
    }

    // ---------------- epilogue: bias + ReLU ----------------
#pragma unroll
    for (int mt = 0; mt < 2; mt++) {
        const int row0 = bm + wm * 32 + mt * 16 + (lane >> 2);
#pragma unroll
        for (int nb = 0; nb < 8; nb++) {
            const int col = bn + wn * 64 + nb * 8 + (lane & 3) * 2;
            const float bx = bias[col];
            const float by = bias[col + 1];
            float y0 = fmaxf(acc[mt][nb][0] + bx, 0.0f);
            float y1 = fmaxf(acc[mt][nb][1] + by, 0.0f);
            float y2 = fmaxf(acc[mt][nb][2] + bx, 0.0f);
            float y3 = fmaxf(acc[mt][nb][3] + by, 0.0f);
            if (WRITE_HILO) {
                __nv_bfloat16 h0 = __float2bfloat16(y0), h1 = __float2bfloat16(y1);
                __nv_bfloat16 h2 = __float2bfloat16(y2), h3 = __float2bfloat16(y3);
                __nv_bfloat16 l0 = __float2bfloat16(y0 - __bfloat162float(h0));
                __nv_bfloat16 l1 = __float2bfloat16(y1 - __bfloat162float(h1));
                __nv_bfloat16 l2 = __float2bfloat16(y2 - __bfloat162float(h2));
                __nv_bfloat16 l3 = __float2bfloat16(y3 - __bfloat162float(h3));
                *(__nv_bfloat162*)(Chi + (size_t)row0 * N + col)       = __nv_bfloat162(h0, h1);
                *(__nv_bfloat162*)(Chi + (size_t)(row0 + 8) * N + col) = __nv_bfloat162(h2, h3);
                *(__nv_bfloat162*)(Clo + (size_t)row0 * N + col)       = __nv_bfloat162(l0, l1);
                *(__nv_bfloat162*)(Clo + (size_t)(row0 + 8) * N + col) = __nv_bfloat162(l2, l3);
            } else {
                *(float2*)(Cf + (size_t)row0 * N + col)       = make_float2(y0, y1);
                *(float2*)(Cf + (size_t)(row0 + 8) * N + col) = make_float2(y2, y3);
            }
        }
    }
}

// ---------------- conversion kernels ----------------
__global__ __launch_bounds__(256)
void split_f32(const float* __restrict__ in, __nv_bfloat16* __restrict__ hi,
               __nv_bfloat16* __restrict__ lo, size_t n4)
{
    size_t i = (size_t)blockIdx.x * blockDim.x + threadIdx.x;
    if (i >= n4) return;
    float4 v = ((const float4*)in)[i];
    __nv_bfloat16 h0 = __float2bfloat16(v.x), h1 = __float2bfloat16(v.y);
    __nv_bfloat16 h2 = __float2bfloat16(v.z), h3 = __float2bfloat16(v.w);
    __nv_bfloat16 l0 = __float2bfloat16(v.x - __bfloat162float(h0));
    __nv_bfloat16 l1 = __float2bfloat16(v.y - __bfloat162float(h1));
    __nv_bfloat16 l2 = __float2bfloat16(v.z - __bfloat162float(h2));
    __nv_bfloat16 l3 = __float2bfloat16(v.w - __bfloat162float(h3));
    ((__nv_bfloat162*)hi)[i * 2 + 0] = __nv_bfloat162(h0, h1);
    ((__nv_bfloat162*)hi)[i * 2 + 1] = __nv_bfloat162(h2, h3);
    ((__nv_bfloat162*)lo)[i * 2 + 0] = __nv_bfloat162(l0, l1);
    ((__nv_bfloat162*)lo)[i * 2 + 1] = __nv_bfloat162(l2, l3);
}

// in: [K][N] fp32 row-major -> out hi/lo: [N][K] bf16 row-major
__global__ __launch_bounds__(256)
void transpose_split(const float* __restrict__ in, __nv_bfloat16* __restrict__ hi,
                     __nv_bfloat16* __restrict__ lo, int K, int N)
{
    __shared__ float t[32][33];
    const int k0 = blockIdx.y * 32;
    const int n0 = blockIdx.x * 32;
    const int tx = threadIdx.x;
    const int ty = threadIdx.y;
#pragma unroll
    for (int r = 0; r < 4; r++) {
        const int k = k0 + ty * 4 + r;
        t[ty * 4 + r][tx] = in[(size_t)k * N + n0 + tx];
    }
    __syncthreads();
#pragma unroll
    for (int r = 0; r < 4; r++) {
        const int n = n0 + ty * 4 + r;
        const float v = t[tx][ty * 4 + r];
        const __nv_bfloat16 h = __float2bfloat16(v);
        const __nv_bfloat16 l = __float2bfloat16(v - __bfloat162float(h));
        hi[(size_t)n * K + k0 + tx] = h;
        lo[(size_t)n * K + k0 + tx] = l;
    }
}

// ---------------- heads ----------------
__global__ __launch_bounds__(256)
void heads_kernel(const float* __restrict__ H,
                  const float* __restrict__ Wc, const float* __restrict__ bc,
                  const float* __restrict__ Wr, const float* __restrict__ br,
                  float* __restrict__ out, int M)
{
    const int warp = (blockIdx.x * blockDim.x + threadIdx.x) >> 5;
    const int lane = threadIdx.x & 31;
    if (warp >= M) return;

    const float* __restrict__ h = H + (size_t)warp * D_HID;
    float acc[16];
#pragma unroll
    for (int c = 0; c < 16; c++) acc[c] = 0.0f;

    for (int k = lane; k < D_HID; k += 32) {
        const float x = h[k];
        const float* wc = Wc + (size_t)k * 4;
#pragma unroll
        for (int c = 0; c < 4; c++) acc[c] = fmaf(x, wc[c], acc[c]);
        const float* wr = Wr + (size_t)k * 12;
#pragma unroll
        for (int c = 0; c < 12; c++) acc[4 + c] = fmaf(x, wr[c], acc[4 + c]);
    }
#pragma unroll
    for (int c = 0; c < 16; c++)
#pragma unroll
        for (int off = 16; off > 0; off >>= 1)
            acc[c] += __shfl_xor_sync(0xffffffffu, acc[c], off);

    if (lane < 4) {
        out[(size_t)warp * 4 + lane] = acc[lane] + bc[lane];
    } else if (lane < 16) {
        out[(size_t)M * 4 + (size_t)warp * 12 + (lane - 4)] = acc[lane] + br[lane - 4];
    }
}

// ---------------- host ----------------
extern "C" void kernel_launch(void* const* d_in, const int* in_sizes, int n_in,
                              void* d_out, int out_size)
{
    const float* X  = (const float*)d_in[0];
    const float* W1 = (const float*)d_in[1];
    const float* b1 = (const float*)d_in[2];
    const float* W2 = (const float*)d_in[3];
    const float* b2 = (const float*)d_in[4];
    const float* Wc = (const float*)d_in[5];
    const float* bc = (const float*)d_in[6];
    const float* Wr = (const float*)d_in[7];
    const float* br = (const float*)d_in[8];
    float* out = (float*)d_out;

    const int M = in_sizes[0] / D_IN;   // 16000

    __nv_bfloat16 *Xhi, *Xlo, *W1hi, *W1lo, *W2hi, *W2lo, *h1hi, *h1lo;
    float* h2;
    cudaGetSymbolAddress((void**)&Xhi, g_Xhi);
    cudaGetSymbolAddress((void**)&Xlo, g_Xlo);
    cudaGetSymbolAddress((void**)&W1hi, g_W1hi);
    cudaGetSymbolAddress((void**)&W1lo, g_W1lo);
    cudaGetSymbolAddress((void**)&W2hi, g_W2hi);
    cudaGetSymbolAddress((void**)&W2lo, g_W2lo);
    cudaGetSymbolAddress((void**)&h1hi, g_h1hi);
    cudaGetSymbolAddress((void**)&h1lo, g_h1lo);
    cudaGetSymbolAddress((void**)&h2, g_h2);

    // conversions
    {
        const size_t n4 = (size_t)M * D_IN / 4;
        split_f32<<<(unsigned)((n4 + 255) / 256), 256>>>(X, Xhi, Xlo, n4);
        dim3 tb(32, 8);
        transpose_split<<<dim3(D_HID / 32, D_IN / 32), tb>>>(W1, W1hi, W1lo, D_IN, D_HID);
        transpose_split<<<dim3(D_HID / 32, D_HID / 32), tb>>>(W2, W2hi, W2lo, D_HID, D_HID);
    }

    cudaFuncSetAttribute(gemm_mma_x3<1>, cudaFuncAttributeMaxDynamicSharedMemorySize, SM_TOTAL);
    cudaFuncSetAttribute(gemm_mma_x3<0>, cudaFuncAttributeMaxDynamicSharedMemorySize, SM_TOTAL);

    dim3 grid(D_HID / 128, M / 128);   // (8, 125) = 1000 CTAs
    gemm_mma_x3<1><<<grid, 256, SM_TOTAL>>>(Xhi, Xlo, W1hi, W1lo, b1, h1hi, h1lo, nullptr, D_IN, D_HID);
    gemm_mma_x3<0><<<grid, 256, SM_TOTAL>>>(h1hi, h1lo, W2hi, W2lo, b2, nullptr, nullptr, h2, D_HID, D_HID);

    const int threads = 256;
    const int blocks = (M * 32 + threads - 1) / threads;
    heads_kernel<<<blocks, threads>>>(h2, Wc, bc, Wr, br, out, M);
}

// round 7
// speedup vs baseline: 1.1231x; 1.0203x over previous
#include <cuda_runtime.h>
#include <cuda_bf16.h>
#include <cstdint>
#include <cstddef>

#define D_IN  12544
#define D_HID 1024
#define MAXN  16000

// ---------------- device scratch (allocation-free rule) ----------------
__device__ __align__(1024) __nv_bfloat16 g_Xhi[(size_t)MAXN * D_IN];
__device__ __align__(1024) __nv_bfloat16 g_Xlo[(size_t)MAXN * D_IN];
__device__ __align__(1024) __nv_bfloat16 g_W1hi[(size_t)D_HID * D_IN];  // [N][K]
__device__ __align__(1024) __nv_bfloat16 g_W1lo[(size_t)D_HID * D_IN];
__device__ __align__(1024) __nv_bfloat16 g_W2hi[(size_t)D_HID * D_HID];
__device__ __align__(1024) __nv_bfloat16 g_W2lo[(size_t)D_HID * D_HID];
__device__ __align__(1024) __nv_bfloat16 g_h1hi[(size_t)MAXN * D_HID];
__device__ __align__(1024) __nv_bfloat16 g_h1lo[(size_t)MAXN * D_HID];
__device__ float g_h2[(size_t)MAXN * D_HID];

// ---------------- asm helpers ----------------
__device__ __forceinline__ uint32_t smem_u32(const void* p) {
    uint32_t a;
    asm("{ .reg .u64 t; cvta.to.shared.u64 t, %1; cvt.u32.u64 %0, t; }" : "=r"(a) : "l"(p));
    return a;
}
__device__ __forceinline__ void cp16(uint32_t dst, const void* src) {
    asm volatile("cp.async.cg.shared.global [%0], [%1], 16;" :: "r"(dst), "l"(src));
}
__device__ __forceinline__ void cp_commit() {
    asm volatile("cp.async.commit_group;" ::: "memory");
}
template <int N>
__device__ __forceinline__ void cp_wait() {
    asm volatile("cp.async.wait_group %0;" :: "n"(N) : "memory");
}
__device__ __forceinline__ void ldm_x4(uint32_t& r0, uint32_t& r1, uint32_t& r2, uint32_t& r3, uint32_t addr) {
    asm volatile("ldmatrix.sync.aligned.m8n8.x4.shared.b16 {%0,%1,%2,%3}, [%4];"
                 : "=r"(r0), "=r"(r1), "=r"(r2), "=r"(r3) : "r"(addr));
}
__device__ __forceinline__ void mma16816(float* c, const uint32_t* a, uint32_t b0, uint32_t b1) {
    asm volatile(
        "mma.sync.aligned.m16n8k16.row.col.f32.bf16.bf16.f32 "
        "{%0,%1,%2,%3}, {%4,%5,%6,%7}, {%8,%9}, {%0,%1,%2,%3};"
        : "+f"(c[0]), "+f"(c[1]), "+f"(c[2]), "+f"(c[3])
        : "r"(a[0]), "r"(a[1]), "r"(a[2]), "r"(a[3]), "r"(b0), "r"(b1));
}

// ---------------- GEMM: C[M,N] = act(A[M,K] @ B[N,K]^T + bias), bf16 hi/lo x3 ----------------
// CTA tile BM=128, BN=128, BK=32. 2-stage cp.async pipeline, 2 CTAs/SM.
// 8 warps (4 M x 2 N), warp tile 32x64.
// Inner schedule is PRODUCT-MAJOR over 8-tile groups so dependent MMAs on the
// same accumulator are 8 apart (was 1 apart) -> hides HMMA latency.
#define LDS       40                    // smem stride in halves (80B) - conflict free
#define TILE_B    (128 * LDS * 2)       // 10240 B per [128][32] bf16 tile
#define OFF_AHI   0
#define OFF_ALO   (TILE_B)
#define OFF_BHI   (2 * TILE_B)
#define OFF_BLO   (3 * TILE_B)
#define STAGE_B   (4 * TILE_B)          // 40960
#define NSTAGE    2
#define SM_TOTAL  (NSTAGE * STAGE_B)    // 81920 -> 2 CTAs/SM

__device__ __forceinline__ void load_tile(uint32_t sdst, const __nv_bfloat16* __restrict__ g,
                                          int row0, int K, int k0, int tid)
{
    const char* gb = (const char*)(g + (size_t)row0 * K + k0);
#pragma unroll
    for (int p = 0; p < 2; p++) {
        const int r = (tid >> 2) + p * 64;
        const int c = tid & 3;
        cp16(sdst + r * (LDS * 2) + c * 16, gb + (size_t)r * K * 2 + c * 16);
    }
}

template <int WRITE_HILO>
__global__ __launch_bounds__(256, 2)
void gemm_mma_x3(const __nv_bfloat16* __restrict__ Ahi, const __nv_bfloat16* __restrict__ Alo,
                 const __nv_bfloat16* __restrict__ Bhi, const __nv_bfloat16* __restrict__ Blo,
                 const float* __restrict__ bias,
                 __nv_bfloat16* __restrict__ Chi, __nv_bfloat16* __restrict__ Clo,
                 float* __restrict__ Cf,
                 int K, int N)
{
    extern __shared__ char smem[];
    const uint32_t sb = smem_u32(smem);
    const int tid  = threadIdx.x;
    const int wid  = tid >> 5;
    const int lane = tid & 31;
    const int wm   = wid & 3;        // 0..3 (M)
    const int wn   = wid >> 2;       // 0..1 (N)

    const int bm = blockIdx.y * 128;
    const int bn = blockIdx.x * 128;
    const int NK = K / 32;

    float acc[2][8][4];
#pragma unroll
    for (int mt = 0; mt < 2; mt++)
#pragma unroll
        for (int nb = 0; nb < 8; nb++)
#pragma unroll
            for (int q = 0; q < 4; q++) acc[mt][nb][q] = 0.0f;

    // prologue: prefetch stage 0
    {
        const uint32_t st = sb;
        load_tile(st + OFF_AHI, Ahi, bm, K, 0, tid);
        load_tile(st + OFF_ALO, Alo, bm, K, 0, tid);
        load_tile(st + OFF_BHI, Bhi, bn, K, 0, tid);
        load_tile(st + OFF_BLO, Blo, bn, K, 0, tid);
        cp_commit();
    }

    // ldmatrix lane addressing (within-tile offsets, in bytes)
    const uint32_t a_lane_off = ((lane & 15) * LDS + (lane >> 4) * 8) * 2;
    const uint32_t b_lane_off = ((((lane >> 4) * 8) + (lane & 7)) * LDS + (((lane >> 3) & 1) * 8)) * 2;
    const uint32_t a_base_off = (wm * 32) * (LDS * 2);
    const uint32_t b_base_off = (wn * 64) * (LDS * 2);

    for (int c = 0; c < NK; c++) {
        cp_wait<0>();
        __syncthreads();

        // prefetch next stage into the other buffer
        const int pf = c + 1;
        if (pf < NK) {
            const uint32_t st = sb + (pf & 1) * STAGE_B;
            load_tile(st + OFF_AHI, Ahi, bm, K, pf * 32, tid);
            load_tile(st + OFF_ALO, Alo, bm, K, pf * 32, tid);
            load_tile(st + OFF_BHI, Bhi, bn, K, pf * 32, tid);
            load_tile(st + OFF_BLO, Blo, bn, K, pf * 32, tid);
        }
        cp_commit();

        const uint32_t st = sb + (c & 1) * STAGE_B;
        const uint32_t sAh = st + OFF_AHI + a_base_off + a_lane_off;
        const uint32_t sAl = st + OFF_ALO + a_base_off + a_lane_off;
        const uint32_t sBh = st + OFF_BHI + b_base_off + b_lane_off;
        const uint32_t sBl = st + OFF_BLO + b_base_off + b_lane_off;

#pragma unroll
        for (int kk = 0; kk < 2; kk++) {
            const uint32_t ko = kk * 16 * 2;
            uint32_t ah[2][4], al[2][4];
#pragma unroll
            for (int mt = 0; mt < 2; mt++) {
                ldm_x4(ah[mt][0], ah[mt][1], ah[mt][2], ah[mt][3], sAh + mt * 16 * (LDS * 2) + ko);
                ldm_x4(al[mt][0], al[mt][1], al[mt][2], al[mt][3], sAl + mt * 16 * (LDS * 2) + ko);
            }
            // B pairs: two 16-col blocks per pp; product-major over 8 tiles
#pragma unroll
            for (int pp = 0; pp < 2; pp++) {
                uint32_t bh[2][4], bl[2][4];
#pragma unroll
                for (int pi = 0; pi < 2; pi++) {
                    const int p = pp * 2 + pi;
                    ldm_x4(bh[pi][0], bh[pi][1], bh[pi][2], bh[pi][3], sBh + p * 16 * (LDS * 2) + ko);
                    ldm_x4(bl[pi][0], bl[pi][1], bl[pi][2], bl[pi][3], sBl + p * 16 * (LDS * 2) + ko);
                }
                // product 1: hi*hi  (8 independent MMAs)
#pragma unroll
                for (int mt = 0; mt < 2; mt++)
#pragma unroll
                    for (int pi = 0; pi < 2; pi++)
#pragma unroll
                        for (int half = 0; half < 2; half++)
                            mma16816(acc[mt][(pp * 2 + pi) * 2 + half], ah[mt],
                                     bh[pi][half * 2], bh[pi][half * 2 + 1]);
                // product 2: hi*lo
#pragma unroll
                for (int mt = 0; mt < 2; mt++)
#pragma unroll
                    for (int pi = 0; pi < 2; pi++)
#pragma unroll
                        for (int half = 0; half < 2; half++)
                            mma16816(acc[mt][(pp * 2 + pi) * 2 + half], ah[mt],
                                     bl[pi][half * 2], bl[pi][half * 2 + 1]);
                // product 3: lo*hi
#pragma unroll
                for (int mt = 0; mt < 2; mt++)
#pragma unroll
                    for (int pi = 0; pi < 2; pi++)
#pragma unroll
                        for (int half = 0; half < 2; half++)
                            mma16816(acc[mt][(pp * 2 + pi) * 2 + half], al[mt],
                                     bh[pi][half * 2], bh[pi][half * 2 + 1]);
            }
        }
        __syncthreads();
    }

    // ---------------- epilogue: bias + ReLU ----------------
#pragma unroll
    for (int mt = 0; mt < 2; mt++) {
        const int row0 = bm + wm * 32 + mt * 16 + (lane >> 2);
#pragma unroll
        for (int nb = 0; nb < 8; nb++) {
            const int col = bn + wn * 64 + nb * 8 + (lane & 3) * 2;
            const float bx = bias[col];
            const float by = bias[col + 1];
            float y0 = fmaxf(acc[mt][nb][0] + bx, 0.0f);
            float y1 = fmaxf(acc[mt][nb][1] + by, 0.0f);
            float y2 = fmaxf(acc[mt][nb][2] + bx, 0.0f);
            float y3 = fmaxf(acc[mt][nb][3] + by, 0.0f);
            if (WRITE_HILO) {
                __nv_bfloat16 h0 = __float2bfloat16(y0), h1 = __float2bfloat16(y1);
                __nv_bfloat16 h2 = __float2bfloat16(y2), h3 = __float2bfloat16(y3);
                __nv_bfloat16 l0 = __float2bfloat16(y0 - __bfloat162float(h0));
                __nv_bfloat16 l1 = __float2bfloat16(y1 - __bfloat162float(h1));
                __nv_bfloat16 l2 = __float2bfloat16(y2 - __bfloat162float(h2));
                __nv_bfloat16 l3 = __float2bfloat16(y3 - __bfloat162float(h3));
                *(__nv_bfloat162*)(Chi + (size_t)row0 * N + col)       = __nv_bfloat162(h0, h1);
                *(__nv_bfloat162*)(Chi + (size_t)(row0 + 8) * N + col) = __nv_bfloat162(h2, h3);
                *(__nv_bfloat162*)(Clo + (size_t)row0 * N + col)       = __nv_bfloat162(l0, l1);
                *(__nv_bfloat162*)(Clo + (size_t)(row0 + 8) * N + col) = __nv_bfloat162(l2, l3);
            } else {
                *(float2*)(Cf + (size_t)row0 * N + col)       = make_float2(y0, y1);
                *(float2*)(Cf + (size_t)(row0 + 8) * N + col) = make_float2(y2, y3);
            }
        }
    }
}

// ---------------- conversion kernels ----------------
__global__ __launch_bounds__(256)
void split_f32(const float* __restrict__ in, __nv_bfloat16* __restrict__ hi,
               __nv_bfloat16* __restrict__ lo, size_t n4)
{
    size_t i = (size_t)blockIdx.x * blockDim.x + threadIdx.x;
    if (i >= n4) return;
    float4 v = ((const float4*)in)[i];
    __nv_bfloat16 h0 = __float2bfloat16(v.x), h1 = __float2bfloat16(v.y);
    __nv_bfloat16 h2 = __float2bfloat16(v.z), h3 = __float2bfloat16(v.w);
    __nv_bfloat16 l0 = __float2bfloat16(v.x - __bfloat162float(h0));
    __nv_bfloat16 l1 = __float2bfloat16(v.y - __bfloat162float(h1));
    __nv_bfloat16 l2 = __float2bfloat16(v.z - __bfloat162float(h2));
    __nv_bfloat16 l3 = __float2bfloat16(v.w - __bfloat162float(h3));
    ((__nv_bfloat162*)hi)[i * 2 + 0] = __nv_bfloat162(h0, h1);
    ((__nv_bfloat162*)hi)[i * 2 + 1] = __nv_bfloat162(h2, h3);
    ((__nv_bfloat162*)lo)[i * 2 + 0] = __nv_bfloat162(l0, l1);
    ((__nv_bfloat162*)lo)[i * 2 + 1] = __nv_bfloat162(l2, l3);
}

// in: [K][N] fp32 row-major -> out hi/lo: [N][K] bf16 row-major
__global__ __launch_bounds__(256)
void transpose_split(const float* __restrict__ in, __nv_bfloat16* __restrict__ hi,
                     __nv_bfloat16* __restrict__ lo, int K, int N)
{
    __shared__ float t[32][33];
    const int k0 = blockIdx.y * 32;
    const int n0 = blockIdx.x * 32;
    const int tx = threadIdx.x;
    const int ty = threadIdx.y;
#pragma unroll
    for (int r = 0; r < 4; r++) {
        const int k = k0 + ty * 4 + r;
        t[ty * 4 + r][tx] = in[(size_t)k * N + n0 + tx];
    }
    __syncthreads();
#pragma unroll
    for (int r = 0; r < 4; r++) {
        const int n = n0 + ty * 4 + r;
        const float v = t[tx][ty * 4 + r];
        const __nv_bfloat16 h = __float2bfloat16(v);
        const __nv_bfloat16 l = __float2bfloat16(v - __bfloat162float(h));
        hi[(size_t)n * K + k0 + tx] = h;
        lo[(size_t)n * K + k0 + tx] = l;
    }
}

// ---------------- heads ----------------
__global__ __launch_bounds__(256)
void heads_kernel(const float* __restrict__ H,
                  const float* __restrict__ Wc, const float* __restrict__ bc,
                  const float* __restrict__ Wr, const float* __restrict__ br,
                  float* __restrict__ out, int M)
{
    const int warp = (blockIdx.x * blockDim.x + threadIdx.x) >> 5;
    const int lane = threadIdx.x & 31;
    if (warp >= M) return;

    const float* __restrict__ h = H + (size_t)warp * D_HID;
    float acc[16];
#pragma unroll
    for (int c = 0; c < 16; c++) acc[c] = 0.0f;

    for (int k = lane; k < D_HID; k += 32) {
        const float x = h[k];
        const float* wc = Wc + (size_t)k * 4;
#pragma unroll
        for (int c = 0; c < 4; c++) acc[c] = fmaf(x, wc[c], acc[c]);
        const float* wr = Wr + (size_t)k * 12;
#pragma unroll
        for (int c = 0; c < 12; c++) acc[4 + c] = fmaf(x, wr[c], acc[4 + c]);
    }
#pragma unroll
    for (int c = 0; c < 16; c++)
#pragma unroll
        for (int off = 16; off > 0; off >>= 1)
            acc[c] += __shfl_xor_sync(0xffffffffu, acc[c], off);

    if (lane < 4) {
        out[(size_t)warp * 4 + lane] = acc[lane] + bc[lane];
    } else if (lane < 16) {
        out[(size_t)M * 4 + (size_t)warp * 12 + (lane - 4)] = acc[lane] + br[lane - 4];
    }
}

// ---------------- host ----------------
extern "C" void kernel_launch(void* const* d_in, const int* in_sizes, int n_in,
                              void* d_out, int out_size)
{
    const float* X  = (const float*)d_in[0];
    const float* W1 = (const float*)d_in[1];
    const float* b1 = (const float*)d_in[2];
    const float* W2 = (const float*)d_in[3];
    const float* b2 = (const float*)d_in[4];
    const float* Wc = (const float*)d_in[5];
    const float* bc = (const float*)d_in[6];
    const float* Wr = (const float*)d_in[7];
    const float* br = (const float*)d_in[8];
    float* out = (float*)d_out;

    const int M = in_sizes[0] / D_IN;   // 16000

    __nv_bfloat16 *Xhi, *Xlo, *W1hi, *W1lo, *W2hi, *W2lo, *h1hi, *h1lo;
    float* h2;
    cudaGetSymbolAddress((void**)&Xhi, g_Xhi);
    cudaGetSymbolAddress((void**)&Xlo, g_Xlo);
    cudaGetSymbolAddress((void**)&W1hi, g_W1hi);
    cudaGetSymbolAddress((void**)&W1lo, g_W1lo);
    cudaGetSymbolAddress((void**)&W2hi, g_W2hi);
    cudaGetSymbolAddress((void**)&W2lo, g_W2lo);
    cudaGetSymbolAddress((void**)&h1hi, g_h1hi);
    cudaGetSymbolAddress((void**)&h1lo, g_h1lo);
    cudaGetSymbolAddress((void**)&h2, g_h2);

    // conversions
    {
        const size_t n4 = (size_t)M * D_IN / 4;
        split_f32<<<(unsigned)((n4 + 255) / 256), 256>>>(X, Xhi, Xlo, n4);
        dim3 tb(32, 8);
        transpose_split<<<dim3(D_HID / 32, D_IN / 32), tb>>>(W1, W1hi, W1lo, D_IN, D_HID);
        transpose_split<<<dim3(D_HID / 32, D_HID / 32), tb>>>(W2, W2hi, W2lo, D_HID, D_HID);
    }

    cudaFuncSetAttribute(gemm_mma_x3<1>, cudaFuncAttributeMaxDynamicSharedMemorySize, SM_TOTAL);
    cudaFuncSetAttribute(gemm_mma_x3<0>, cudaFuncAttributeMaxDynamicSharedMemorySize, SM_TOTAL);

    dim3 grid(D_HID / 128, M / 128);   // (8, 125) = 1000 CTAs
    gemm_mma_x3<1><<<grid, 256, SM_TOTAL>>>(Xhi, Xlo, W1hi, W1lo, b1, h1hi, h1lo, nullptr, D_IN, D_HID);
    gemm_mma_x3<0><<<grid, 256, SM_TOTAL>>>(h1hi, h1lo, W2hi, W2lo, b2, nullptr, nullptr, h2, D_HID, D_HID);

    const int threads = 256;
    const int blocks = (M * 32 + threads - 1) / threads;
    heads_kernel<<<blocks, threads>>>(h2, Wc, bc, Wr, br, out, M);
}